// round 2
// baseline (speedup 1.0000x reference)
#include <cuda_runtime.h>
#include <math.h>

// Problem constants (fixed by setup_inputs)
#define NN 16
#define CC 30
#define HH 128
#define WW 128
#define HWSZ (HH*WW)          // 16384
#define PERB (CC*HWSZ)        // 491520 per-batch elements
#define TOT (NN*PERB)         // 7,864,320
#define NB 16384              // histogram buckets per batch
#define CAP 2048              // candidate capacity per batch
// Permissive logit threshold: logit(0.3) = -0.8472978...; slack harmless (final
// validity is re-checked via exact f32 sigmoid > 0.3f; rank-1000 cutoff ~0.78).
#define XLO (-0.84733f)
#define BSHIFT 0.85f
#define BSCALE ((float)NB/6.0f)

// Scratch (device globals; no allocation anywhere)
__device__ unsigned g_hist[NN*NB];            // 1 MB
__device__ unsigned g_cutB[NN];
__device__ unsigned g_cnt[NN];
__device__ unsigned long long g_cand[NN*CAP]; // 256 KB: (logit bits << 32) | flat_idx

__device__ __forceinline__ int bucket_of(float x){
    int b = (int)((x + BSHIFT) * BSCALE);     // monotone for x > -BSHIFT
    return min(max(b, 0), NB-1);
}

__global__ void k_zero(){
    int i = blockIdx.x*blockDim.x + threadIdx.x;
    if (i < NN*NB) g_hist[i] = 0u;
    if (i < NN) g_cnt[i] = 0u;
}

__global__ void k_hist(const float* __restrict__ sCls){
    int stride = gridDim.x * blockDim.x;
    for (int v = blockIdx.x*blockDim.x + threadIdx.x; v < TOT/4; v += stride){
        float4 x4 = ((const float4* __restrict__)sCls)[v];
        int n = (v*4) / PERB;   // PERB % 4 == 0 -> uniform within the vector
        unsigned* h = &g_hist[n*NB];
        if (x4.x > XLO) atomicAdd(&h[bucket_of(x4.x)], 1u);
        if (x4.y > XLO) atomicAdd(&h[bucket_of(x4.y)], 1u);
        if (x4.z > XLO) atomicAdd(&h[bucket_of(x4.z)], 1u);
        if (x4.w > XLO) atomicAdd(&h[bucket_of(x4.w)], 1u);
    }
}

// One block per batch: cutoff bucket B = max{b : sum_{j>=b} hist[j] >= K} (0 if total < K)
__global__ void k_scan(int K){
    int n = blockIdx.x, t = threadIdx.x;   // 256 threads
    __shared__ unsigned part[256];
    __shared__ unsigned chunkv[64];
    __shared__ int s_tc;
    __shared__ unsigned s_above;
    const unsigned* h = &g_hist[n*NB];
    unsigned s = 0;
    #pragma unroll 8
    for (int j = 0; j < 64; j++) s += h[t*64 + j];
    part[t] = s;
    __syncthreads();
    if (t == 0){
        unsigned acc = 0; int tc = -1; unsigned above = 0;
        for (int j = 255; j >= 0; j--){
            unsigned na = acc + part[j];
            if (na >= (unsigned)K){ tc = j; above = acc; break; }
            acc = na;
        }
        s_tc = tc; s_above = above;
        if (tc < 0) g_cutB[n] = 0u;
    }
    __syncthreads();
    int tc = s_tc;
    if (tc < 0) return;
    if (t < 64) chunkv[t] = h[tc*64 + t];
    __syncthreads();
    if (t == 0){
        unsigned acc = s_above; int B = tc*64;
        for (int b = 63; b >= 0; b--){
            acc += chunkv[b];
            if (acc >= (unsigned)K){ B = tc*64 + b; break; }
        }
        g_cutB[n] = (unsigned)B;
    }
}

__device__ __forceinline__ void try_collect(float x, int i, int n, unsigned cutB){
    if (x <= XLO) return;
    if ((unsigned)bucket_of(x) < cutB) return;
    unsigned pos = atomicAdd(&g_cnt[n], 1u);
    if (pos < CAP){
        int r  = i - n*PERB;
        int c  = r / HWSZ;
        int hw = r - c*HWSZ;
        unsigned idx = (unsigned)(hw*CC + c);   // reference flat index = loc*C + class
        g_cand[n*CAP + pos] = ((unsigned long long)__float_as_uint(x) << 32) | idx;
    }
}

__global__ void k_collect(const float* __restrict__ sCls){
    int stride = gridDim.x * blockDim.x;
    for (int v = blockIdx.x*blockDim.x + threadIdx.x; v < TOT/4; v += stride){
        float4 x4 = ((const float4* __restrict__)sCls)[v];
        int i = v*4;
        int n = i / PERB;
        unsigned cutB = g_cutB[n];
        try_collect(x4.x, i+0, n, cutB);
        try_collect(x4.y, i+1, n, cutB);
        try_collect(x4.z, i+2, n, cutB);
        try_collect(x4.w, i+3, n, cutB);
    }
}

// One block per batch: exact sigmoid (double -> faithfully-rounded f32) for candidates,
// bitonic sort by (sigmoid desc, index asc), decode boxes, emit outputs.
__global__ void __launch_bounds__(1024) k_emit(const float* __restrict__ sReg,
                                               const float* __restrict__ anchors,
                                               float* __restrict__ out, int K){
    __shared__ unsigned long long sk[CAP];     // 16 KB
    int n = blockIdx.x, t = threadIdx.x;
    unsigned M = min(g_cnt[n], (unsigned)CAP);

    for (int i = t; i < CAP; i += 1024){
        unsigned long long key = 0ull;
        if (i < (int)M){
            unsigned long long e = g_cand[n*CAP + i];
            float x = __uint_as_float((unsigned)(e >> 32));
            unsigned idx = (unsigned)e;
            float v = (float)(1.0 / (1.0 + exp(-(double)x)));   // correctly-rounded f32 sigmoid
            unsigned ov = __float_as_uint(v) | 0x80000000u;      // v>0: bits ordered ascending
            key = ((unsigned long long)ov << 32) | (unsigned)(~idx); // ties -> smaller idx first
        }
        sk[i] = key;
    }
    __syncthreads();

    // Bitonic sort, descending
    for (int ksz = 2; ksz <= CAP; ksz <<= 1){
        for (int j = ksz >> 1; j > 0; j >>= 1){
            for (int i = t; i < CAP; i += 1024){
                int ixj = i ^ j;
                if (ixj > i){
                    bool desc = ((i & ksz) == 0);
                    unsigned long long a = sk[i], b = sk[ixj];
                    if (desc ? (a < b) : (a > b)){ sk[i] = b; sk[ixj] = a; }
                }
            }
            __syncthreads();
        }
    }

    // Emit: detections [N,K,16] | labels [N,K] | scores [N,K], all as f32
    unsigned nvalid = min(M, (unsigned)K);
    for (int j = t; j < K; j += 1024){
        float* det = out + ((size_t)n*K + j)*16;
        float* lab = out + (size_t)NN*K*16 + (size_t)n*K + j;
        float* sco = out + (size_t)NN*K*17 + (size_t)n*K + j;
        bool valid = false;
        if (j < (int)nvalid){
            unsigned long long key = sk[j];
            unsigned ov = (unsigned)(key >> 32);
            float v = __uint_as_float(ov ^ 0x80000000u);
            if (v > 0.3f){
                valid = true;
                unsigned idx = ~(unsigned)(key & 0xFFFFFFFFull);
                int loc = idx / CC;
                int cls = idx - loc*CC;
                float4 anc = *(const float4*)(anchors + (size_t)loc*4);
                float wa = anc.z - anc.x, ha = anc.w - anc.y;
                float cx = 0.5f*(anc.x + anc.z), cy = 0.5f*(anc.y + anc.w);
                // sReg[n, cls*16 + q, h, w] with loc = h*W + w
                const float* rb = sReg + (((size_t)n*(CC*16) + (size_t)cls*16)*HWSZ + loc);
                #pragma unroll
                for (int q = 0; q < 8; q++)  det[q]     = rb[(size_t)q*HWSZ]     * wa + cx;
                #pragma unroll
                for (int q = 0; q < 8; q++)  det[8 + q] = rb[(size_t)(8+q)*HWSZ] * ha + cy;
                *lab = (float)(cls + 1);
                *sco = sqrtf(v);
            }
        }
        if (!valid){
            #pragma unroll
            for (int q = 0; q < 16; q++) det[q] = 0.0f;
            *lab = 0.0f;
            *sco = 0.0f;
        }
    }
}

extern "C" void kernel_launch(void* const* d_in, const int* in_sizes, int n_in,
                              void* d_out, int out_size){
    const float* sCls    = (const float*)d_in[0];
    const float* sReg    = (const float*)d_in[1];
    const float* anchors = (const float*)d_in[2];
    float* out = (float*)d_out;
    int K = out_size / (NN * 18);   // detections(16) + labels(1) + scores(1) per (n,k)
    if (K < 1) K = 1;
    if (K > CAP) K = CAP;

    k_zero   <<<(NN*NB + 255)/256, 256>>>();
    k_hist   <<<1184, 256>>>(sCls);     // 8 waves of vec4 work over 148 SMs
    k_scan   <<<NN, 256>>>(K);
    k_collect<<<1184, 256>>>(sCls);
    k_emit   <<<NN, 1024>>>(sReg, anchors, out, K);
}